// round 11
// baseline (speedup 1.0000x reference)
#include <cuda_runtime.h>

#define I_DIM 28
#define H_DIM 64
#define T_DIM 128
#define B_DIM 4096
#define OUT_DIM 10
#define TI (T_DIM * I_DIM)          // 3584
#define ROWS 14                     // batch rows per CTA (7 pairs)
#define THREADS 128
#define NBLOCKS 293                 // ceil(4096/14); 2 CTAs co-resident per SM
#define SM_COUNT 152
#define ST 10                       // pair-row stride in u64 (80B, 16B-aligned)
#define ST_F 20

typedef unsigned long long u64;

__device__ __forceinline__ u64 pack2(float lo, float hi) {
    u64 r; asm("mov.b64 %0, {%1, %2};" : "=l"(r) : "f"(lo), "f"(hi)); return r;
}
__device__ __forceinline__ void unpack2(u64 v, float& lo, float& hi) {
    asm("mov.b64 {%0, %1}, %2;" : "=f"(lo), "=f"(hi) : "l"(v));
}
__device__ __forceinline__ u64 ffma2(u64 a, u64 b, u64 c) {
    u64 d; asm("fma.rn.f32x2 %0, %1, %2, %3;" : "=l"(d) : "l"(a), "l"(b), "l"(c)); return d;
}
// ---- PROVEN activations (end-to-end rel_err 2.9e-7; tanh.approx is NOT safe here) ----
__device__ __forceinline__ float rcpa(float x) { float r; asm("rcp.approx.f32 %0, %1;" : "=f"(r) : "f"(x)); return r; }
__device__ __forceinline__ float ex2a(float x) { float r; asm("ex2.approx.f32 %0, %1;" : "=f"(r) : "f"(x)); return r; }
__device__ __forceinline__ float sigm(float x)  { return rcpa(1.0f + ex2a(-1.4426950408889634f * x)); }
__device__ __forceinline__ float tanh_(float x) { return fmaf(2.0f, rcpa(1.0f + ex2a(-2.8853900817779268f * x)), -1.0f); }

// smem (bytes): sWhh 65536 | sWih 28672 | sb 1024 | shT 2x64x10 u64 = 10240 | sxT 2x28x10 u64 = 4480
#define SMEM_BYTES (65536 + 28672 + 1024 + 10240 + 4480)   // 109952; x2 = 219904 <= 232448/SM

template<int NR, int NP, int PB>
__device__ __forceinline__ void accum(const float4* __restrict__ Wm,
                                      const u64* __restrict__ vbuf,
                                      int u, u64* a0, u64* a1, u64* a2, u64* a3)
{
    #pragma unroll 4
    for (int r = 0; r < NR; ++r) {
        float4 w = Wm[(r << 6) + u];
        u64 wi = pack2(w.x, w.x), wf = pack2(w.y, w.y);
        u64 wg = pack2(w.z, w.z), wo = pack2(w.w, w.w);
        const u64* vr = vbuf + r * ST;
        u64 v[NP];
        if constexpr (NP == 4) {
            ulonglong2 p0 = *(const ulonglong2*)(vr + PB);
            ulonglong2 p1 = *(const ulonglong2*)(vr + PB + 2);
            v[0] = p0.x; v[1] = p0.y; v[2] = p1.x; v[3] = p1.y;
        } else {  // NP == 3, PB == 4 (slots 4,5,6)
            ulonglong2 p0 = *(const ulonglong2*)(vr + 4);
            v[0] = p0.x; v[1] = p0.y; v[2] = vr[6];
        }
        #pragma unroll
        for (int j = 0; j < NP; ++j) {
            a0[j] = ffma2(wi, v[j], a0[j]);
            a1[j] = ffma2(wf, v[j], a1[j]);
            a2[j] = ffma2(wg, v[j], a2[j]);
            a3[j] = ffma2(wo, v[j], a3[j]);
        }
    }
}

template<int NP, int PB>
__device__ __forceinline__ void store_h(u64* __restrict__ hrow, const u64* hn)
{
    if constexpr (NP == 4) {
        *(ulonglong2*)(hrow + PB)     = make_ulonglong2(hn[0], hn[1]);
        *(ulonglong2*)(hrow + PB + 2) = make_ulonglong2(hn[2], hn[3]);
    } else {
        *(ulonglong2*)(hrow + 4) = make_ulonglong2(hn[0], hn[1]);
        hrow[6] = hn[2];
    }
}

// One LSTM step chain for this thread's NP row-pairs. CTA-wide barrier per step;
// cross-CTA overlap comes from the independent co-resident CTA.
template<int NP, int PB>
__device__ __forceinline__ void mainloop(
    const float4* __restrict__ sWih, const float4* __restrict__ sWhh,
    u64* __restrict__ shT, u64* __restrict__ sxT,
    int u, u64 bi, u64 bf, u64 bg, u64 bo,
    const float* const* xq, const bool* gg, const bool* vv, const int* sl)
{
    float cc[2 * NP];
    #pragma unroll
    for (int j = 0; j < 2 * NP; ++j) cc[j] = 0.0f;

    for (int t = 0; t < T_DIM; ++t) {
        const int cur = t & 1, nxt = cur ^ 1;
        // prefetch x(t+1) from gmem (hidden under GEMM)
        float xr[4];
        if (t + 1 < T_DIM) {
            #pragma unroll
            for (int j = 0; j < 4; ++j)
                xr[j] = gg[j] ? xq[j][(t + 1) * I_DIM] : 0.0f;
        }

        u64 a0[NP], a1[NP], a2[NP], a3[NP];
        #pragma unroll
        for (int j = 0; j < NP; ++j) { a0[j] = bi; a1[j] = bf; a2[j] = bg; a3[j] = bo; }

        accum<I_DIM, NP, PB>(sWih, sxT + cur * (I_DIM * ST), u, a0, a1, a2, a3);
        accum<H_DIM, NP, PB>(sWhh, shT + cur * (H_DIM * ST), u, a0, a1, a2, a3);

        // epilogue
        u64 hn[NP];
        #pragma unroll
        for (int j = 0; j < NP; ++j) {
            float v0, v1;
            unpack2(a0[j], v0, v1); float i0 = sigm(v0),   i1 = sigm(v1);
            unpack2(a1[j], v0, v1); float f0 = sigm(v0),   f1 = sigm(v1);
            unpack2(a2[j], v0, v1); float g0_ = tanh_(v0), g1_ = tanh_(v1);
            unpack2(a3[j], v0, v1); float o0 = sigm(v0),   o1 = sigm(v1);
            float c0 = fmaf(f0, cc[2 * j],     i0 * g0_);
            float c1 = fmaf(f1, cc[2 * j + 1], i1 * g1_);
            cc[2 * j] = c0; cc[2 * j + 1] = c1;
            hn[j] = pack2(o0 * tanh_(c0), o1 * tanh_(c1));
        }
        store_h<NP, PB>(shT + nxt * (H_DIM * ST) + u * ST, hn);

        // stage x(t+1) into next buffer
        if (t + 1 < T_DIM) {
            float* xd = (float*)(sxT + nxt * (I_DIM * ST));
            #pragma unroll
            for (int j = 0; j < 4; ++j)
                if (vv[j]) xd[sl[j]] = xr[j];
        }
        __syncthreads();   // 4-warp CTA barrier
    }
}

__global__ void __launch_bounds__(THREADS)
lstm_kernel(const float* __restrict__ x,
            const float* __restrict__ W_ih,
            const float* __restrict__ W_hh,
            const float* __restrict__ b_ih,
            const float* __restrict__ b_hh,
            const float* __restrict__ W_out,
            const float* __restrict__ b_out,
            float* __restrict__ out)
{
    extern __shared__ float smem_f[];
    float4* sWhh = (float4*)smem_f;
    float4* sWih = sWhh + H_DIM * H_DIM;
    float4* sb   = sWih + I_DIM * H_DIM;
    u64*    shT  = (u64*)(sb + H_DIM);        // 2 x [k][ST]
    u64*    sxT  = shT + 2 * H_DIM * ST;      // 2 x [i][ST]

    const int tid  = threadIdx.x;
    const int wid  = tid >> 5;
    const int lane = tid & 31;
    const int g    = wid & 1;                 // group: warps {g, g+2}
    const int u    = ((wid >> 1) << 5) | lane; // hidden unit 0..63
    // SMSP-balance flip across co-resident CTAs (bid and bid+152 share an SM):
    // for bid < 152 group0 takes NP4; for bid >= 152 group1 takes NP4.
    const int flip = (blockIdx.x >= SM_COUNT) ? 1 : 0;
    const bool np4 = ((g ^ flip) == 0);       // NP4 -> pairs [0,4), NP3 -> pairs [4,7)
    const int row0 = blockIdx.x * ROWS;

    // ---- weight staging (gate-interleaved float4, [row][u]) ----
    for (int idx = tid; idx < I_DIM * H_DIM; idx += THREADS) {
        int uu = idx & 63, ii = idx >> 6;
        sWih[ii * H_DIM + uu] = make_float4(
            W_ih[uu * I_DIM + ii],
            W_ih[(64 + uu) * I_DIM + ii],
            W_ih[(128 + uu) * I_DIM + ii],
            W_ih[(192 + uu) * I_DIM + ii]);
    }
    for (int idx = tid; idx < H_DIM * H_DIM; idx += THREADS) {
        int uu = idx & 63, kk = idx >> 6;
        sWhh[kk * H_DIM + uu] = make_float4(
            W_hh[uu * H_DIM + kk],
            W_hh[(64 + uu) * H_DIM + kk],
            W_hh[(128 + uu) * H_DIM + kk],
            W_hh[(192 + uu) * H_DIM + kk]);
    }
    if (tid < H_DIM) {
        sb[tid] = make_float4(b_ih[tid] + b_hh[tid],
                              b_ih[64 + tid] + b_hh[64 + tid],
                              b_ih[128 + tid] + b_hh[128 + tid],
                              b_ih[192 + tid] + b_hh[192 + tid]);
    }
    for (int idx = tid; idx < H_DIM * ST; idx += THREADS) shT[idx] = 0ull;  // h(0)=0

    // ---- per-thread x assignments (392 = 14 rows * 28 elems; 4 rounds of 128) ----
    int sl[4]; bool vv[4], gg[4]; const float* xq[4];
    #pragma unroll
    for (int j = 0; j < 4; ++j) {
        int e = tid + j * THREADS;
        vv[j] = (e < ROWS * I_DIM);
        int ec = vv[j] ? e : 0;
        int r = ec / I_DIM, ii = ec - r * I_DIM;
        int grow = row0 + r;
        gg[j] = vv[j] && (grow < B_DIM);
        xq[j] = x + (size_t)(gg[j] ? grow : 0) * TI + ii;
        sl[j] = ii * ST_F + r;                // float idx: pair r/2, half r%2 -> r
    }
    // stage x(0) into buffer 0
    {
        float* x0 = (float*)sxT;
        #pragma unroll
        for (int j = 0; j < 4; ++j)
            if (vv[j]) x0[sl[j]] = gg[j] ? xq[j][0] : 0.0f;
    }

    __syncthreads();   // weights + biases + h0 + x0 visible
    float4 bv = sb[u];
    u64 bi = pack2(bv.x, bv.x), bf = pack2(bv.y, bv.y);
    u64 bg = pack2(bv.z, bv.z), bo = pack2(bv.w, bv.w);

    if (np4) mainloop<4, 0>(sWih, sWhh, shT, sxT, u, bi, bf, bg, bo, xq, gg, vv, sl);
    else     mainloop<3, 4>(sWih, sWhh, shT, sxT, u, bi, bf, bg, bo, xq, gg, vv, sl);

    // ---- output head: T=128 even -> final h in buffer 0; h[k][r] at float k*ST_F + r ----
    const float* hf = (const float*)shT;
    for (int e = tid; e < ROWS * OUT_DIM; e += THREADS) {
        int r = e / OUT_DIM, o = e - r * OUT_DIM;
        if (row0 + r < B_DIM) {
            float a = b_out[o];
            #pragma unroll
            for (int k = 0; k < H_DIM; ++k)
                a = fmaf(hf[k * ST_F + r], W_out[o * H_DIM + k], a);
            out[(size_t)(row0 + r) * OUT_DIM + o] = a;
        }
    }
}

extern "C" void kernel_launch(void* const* d_in, const int* in_sizes, int n_in,
                              void* d_out, int out_size) {
    const float* x     = (const float*)d_in[0];
    const float* W_ih  = (const float*)d_in[1];
    const float* W_hh  = (const float*)d_in[2];
    const float* b_ih  = (const float*)d_in[3];
    const float* b_hh  = (const float*)d_in[4];
    const float* W_out = (const float*)d_in[5];
    const float* b_out = (const float*)d_in[6];
    float* out = (float*)d_out;

    cudaFuncSetAttribute(lstm_kernel, cudaFuncAttributeMaxDynamicSharedMemorySize, SMEM_BYTES);
    lstm_kernel<<<NBLOCKS, THREADS, SMEM_BYTES>>>(x, W_ih, W_hh, b_ih, b_hh, W_out, b_out, out);
}

// round 13
// speedup vs baseline: 1.2587x; 1.2587x over previous
#include <cuda_runtime.h>

#define I_DIM 28
#define H_DIM 64
#define T_DIM 128
#define B_DIM 4096
#define OUT_DIM 10
#define TI (T_DIM * I_DIM)          // 3584
#define ROWS 28                     // batch rows per CTA (14 pairs)
#define THREADS 256
#define NBLOCKS 147                 // one CTA per SM
#define ST 18                       // pair-row stride in u64 (144B)
#define ST_F 36

typedef unsigned long long u64;

__device__ __forceinline__ u64 pack2(float lo, float hi) {
    u64 r; asm("mov.b64 %0, {%1, %2};" : "=l"(r) : "f"(lo), "f"(hi)); return r;
}
__device__ __forceinline__ void unpack2(u64 v, float& lo, float& hi) {
    asm("mov.b64 {%0, %1}, %2;" : "=f"(lo), "=f"(hi) : "l"(v));
}
__device__ __forceinline__ u64 ffma2(u64 a, u64 b, u64 c) {
    u64 d; asm("fma.rn.f32x2 %0, %1, %2, %3;" : "=l"(d) : "l"(a), "l"(b), "l"(c)); return d;
}
// ---- PROVEN activations (end-to-end rel_err 2.9e-7; tanh.approx is NOT safe here) ----
__device__ __forceinline__ float rcpa(float x) { float r; asm("rcp.approx.f32 %0, %1;" : "=f"(r) : "f"(x)); return r; }
__device__ __forceinline__ float ex2a(float x) { float r; asm("ex2.approx.f32 %0, %1;" : "=f"(r) : "f"(x)); return r; }
__device__ __forceinline__ float sigm(float x)  { return rcpa(1.0f + ex2a(-1.4426950408889634f * x)); }
__device__ __forceinline__ float tanh_(float x) { return fmaf(2.0f, rcpa(1.0f + ex2a(-2.8853900817779268f * x)), -1.0f); }

__device__ __forceinline__ void bar_group(int barid) {
    asm volatile("bar.sync %0, 64;" :: "r"(barid) : "memory");
}

// smem (bytes): sWhh 65536 | sWih 28672 | sb 1024 | shT 2x64x18 u64 = 18432 | sxT 2x28x18 u64 = 8064
#define SMEM_BYTES (65536 + 28672 + 1024 + 18432 + 8064)   // 121728

template<int NR, int NP>
__device__ __forceinline__ void accum(const float4* __restrict__ Wm,
                                      const u64* __restrict__ vbuf,
                                      int u, int pb, u64* a0, u64* a1, u64* a2, u64* a3)
{
    #pragma unroll 4
    for (int r = 0; r < NR; ++r) {
        float4 w = Wm[(r << 6) + u];
        u64 wi = pack2(w.x, w.x), wf = pack2(w.y, w.y);
        u64 wg = pack2(w.z, w.z), wo = pack2(w.w, w.w);
        const u64* vr = vbuf + r * ST;
        u64 v[NP];
        if constexpr (NP == 4) {  // pb in {0,4}: 16B-aligned
            ulonglong2 p0 = *(const ulonglong2*)(vr + pb);
            ulonglong2 p1 = *(const ulonglong2*)(vr + pb + 2);
            v[0] = p0.x; v[1] = p0.y; v[2] = p1.x; v[3] = p1.y;
        } else {                  // pb in {8,11}: scalar u64 loads (alignment-safe)
            v[0] = vr[pb]; v[1] = vr[pb + 1]; v[2] = vr[pb + 2];
        }
        #pragma unroll
        for (int j = 0; j < NP; ++j) {
            a0[j] = ffma2(wi, v[j], a0[j]);
            a1[j] = ffma2(wf, v[j], a1[j]);
            a2[j] = ffma2(wg, v[j], a2[j]);
            a3[j] = ffma2(wo, v[j], a3[j]);
        }
    }
}

template<int NP>
__device__ __forceinline__ void store_h(u64* __restrict__ hrow, int pb, const u64* hn)
{
    if constexpr (NP == 4) {
        *(ulonglong2*)(hrow + pb)     = make_ulonglong2(hn[0], hn[1]);
        *(ulonglong2*)(hrow + pb + 2) = make_ulonglong2(hn[2], hn[3]);
    } else {
        hrow[pb] = hn[0]; hrow[pb + 1] = hn[1]; hrow[pb + 2] = hn[2];
    }
}

template<int NP>
__device__ __forceinline__ void epilogue(u64* a0, u64* a1, u64* a2, u64* a3,
                                         float* cc, u64* hn)
{
    #pragma unroll
    for (int j = 0; j < NP; ++j) {
        float v0, v1;
        unpack2(a0[j], v0, v1); float i0 = sigm(v0),   i1 = sigm(v1);
        unpack2(a1[j], v0, v1); float f0 = sigm(v0),   f1 = sigm(v1);
        unpack2(a2[j], v0, v1); float g0_ = tanh_(v0), g1_ = tanh_(v1);
        unpack2(a3[j], v0, v1); float o0 = sigm(v0),   o1 = sigm(v1);
        float c0 = fmaf(f0, cc[2 * j],     i0 * g0_);
        float c1 = fmaf(f1, cc[2 * j + 1], i1 * g1_);
        cc[2 * j] = c0; cc[2 * j + 1] = c1;
        hn[j] = pack2(o0 * tanh_(c0), o1 * tanh_(c1));
    }
}

// ORD=0: X(t) -> H(t) -> epi -> stage x(t+1).   ORD=1: H(t) -> epi -> X(t+1) -> stage x(t+2).
// Paired per SMSP (one ORD0 warp + one ORD1 warp), the epilogue MUFU windows are
// phase-offset BY CONSTRUCTION so one warp's MUFU overlaps the other's FFMA2 GEMM.
template<int NP, int ORD>
__device__ __forceinline__ void mainloop(
    const float4* __restrict__ sWih, const float4* __restrict__ sWhh,
    u64* __restrict__ shT, u64* __restrict__ sxT,
    int u, int pb, int barid, u64 bi, u64 bf, u64 bg, u64 bo,
    const float* const* xq, const bool* gg, const bool* vv, const int* sl)
{
    float cc[2 * NP];
    #pragma unroll
    for (int j = 0; j < 2 * NP; ++j) cc[j] = 0.0f;

    u64 a0[NP], a1[NP], a2[NP], a3[NP];
    if constexpr (ORD == 1) {   // carried partial: bias + X(0) from buffer 0
        #pragma unroll
        for (int j = 0; j < NP; ++j) { a0[j] = bi; a1[j] = bf; a2[j] = bg; a3[j] = bo; }
        accum<I_DIM, NP>(sWih, sxT, u, pb, a0, a1, a2, a3);
    }

    for (int t = 0; t < T_DIM; ++t) {
        const int cur = t & 1, nxt = cur ^ 1;
        const int ahead = (ORD == 0) ? 1 : 2;
        const bool pf = (t + ahead < T_DIM);
        float xr[NP];
        if (pf) {
            #pragma unroll
            for (int j = 0; j < NP; ++j)
                xr[j] = gg[j] ? xq[j][(t + ahead) * I_DIM] : 0.0f;
        }

        u64 hn[NP];
        if constexpr (ORD == 0) {
            #pragma unroll
            for (int j = 0; j < NP; ++j) { a0[j] = bi; a1[j] = bf; a2[j] = bg; a3[j] = bo; }
            accum<I_DIM, NP>(sWih, sxT + cur * (I_DIM * ST), u, pb, a0, a1, a2, a3);
            accum<H_DIM, NP>(sWhh, shT + cur * (H_DIM * ST), u, pb, a0, a1, a2, a3);
            epilogue<NP>(a0, a1, a2, a3, cc, hn);
            store_h<NP>(shT + nxt * (H_DIM * ST) + u * ST, pb, hn);
            if (pf) {   // stage x(t+1) into next buffer
                float* xd = (float*)(sxT + nxt * (I_DIM * ST));
                #pragma unroll
                for (int j = 0; j < NP; ++j)
                    if (vv[j]) xd[sl[j]] = xr[j];
            }
        } else {
            accum<H_DIM, NP>(sWhh, shT + cur * (H_DIM * ST), u, pb, a0, a1, a2, a3);
            epilogue<NP>(a0, a1, a2, a3, cc, hn);
            store_h<NP>(shT + nxt * (H_DIM * ST) + u * ST, pb, hn);
            if (t + 1 < T_DIM) {   // rebuild partial for t+1 (reads buf staged at t-1)
                #pragma unroll
                for (int j = 0; j < NP; ++j) { a0[j] = bi; a1[j] = bf; a2[j] = bg; a3[j] = bo; }
                accum<I_DIM, NP>(sWih, sxT + nxt * (I_DIM * ST), u, pb, a0, a1, a2, a3);
            }
            if (pf) {   // stage x(t+2) into buf t&1 (read two iters from now)
                float* xd = (float*)(sxT + cur * (I_DIM * ST));
                #pragma unroll
                for (int j = 0; j < NP; ++j)
                    if (vv[j]) xd[sl[j]] = xr[j];
            }
        }
        bar_group(barid);   // 64-thread group barrier — groups stay phase-offset
    }
}

__global__ void __launch_bounds__(THREADS, 1)
lstm_kernel(const float* __restrict__ x,
            const float* __restrict__ W_ih,
            const float* __restrict__ W_hh,
            const float* __restrict__ b_ih,
            const float* __restrict__ b_hh,
            const float* __restrict__ W_out,
            const float* __restrict__ b_out,
            float* __restrict__ out)
{
    extern __shared__ float smem_f[];
    float4* sWhh = (float4*)smem_f;
    float4* sWih = sWhh + H_DIM * H_DIM;
    float4* sb   = sWih + I_DIM * H_DIM;
    u64*    shT  = (u64*)(sb + H_DIM);        // 2 x [k][ST]
    u64*    sxT  = shT + 2 * H_DIM * ST;      // 2 x [i][ST]

    const int tid  = threadIdx.x;
    const int wid  = tid >> 5;
    const int lane = tid & 31;
    // group q = warps {2q, 2q+1} -> SMSPs {0,1} or {2,3}. Each SMSP hosts one
    // ORDER0 (q<2, NP4) warp and one ORDER1 (q>=2, NP3) warp.
    const int q = wid >> 1;
    const int u = ((wid & 1) << 5) | lane;    // hidden unit 0..63 within group
    const int np = (q < 2) ? 4 : 3;
    const int pb = (q == 0) ? 0 : (q == 1) ? 4 : (q == 2) ? 8 : 11;
    const int barid = q + 1;
    const int row0 = blockIdx.x * ROWS;

    // ---- weight staging (gate-interleaved float4, [row][u]) ----
    for (int idx = tid; idx < I_DIM * H_DIM; idx += THREADS) {
        int uu = idx & 63, ii = idx >> 6;
        sWih[ii * H_DIM + uu] = make_float4(
            W_ih[uu * I_DIM + ii],
            W_ih[(64 + uu) * I_DIM + ii],
            W_ih[(128 + uu) * I_DIM + ii],
            W_ih[(192 + uu) * I_DIM + ii]);
    }
    for (int idx = tid; idx < H_DIM * H_DIM; idx += THREADS) {
        int uu = idx & 63, kk = idx >> 6;
        sWhh[kk * H_DIM + uu] = make_float4(
            W_hh[uu * H_DIM + kk],
            W_hh[(64 + uu) * H_DIM + kk],
            W_hh[(128 + uu) * H_DIM + kk],
            W_hh[(192 + uu) * H_DIM + kk]);
    }
    if (tid < H_DIM) {
        sb[tid] = make_float4(b_ih[tid] + b_hh[tid],
                              b_ih[64 + tid] + b_hh[64 + tid],
                              b_ih[128 + tid] + b_hh[128 + tid],
                              b_ih[192 + tid] + b_hh[192 + tid]);
    }
    for (int idx = tid; idx < H_DIM * ST; idx += THREADS) shT[idx] = 0ull;  // h(0)=0

    // ---- group-local x assignments: group q owns rows [2*pb, 2*pb+2*np) ----
    const int nelems = 2 * np * I_DIM;        // 224 (np4) or 168 (np3)
    int sl[4]; bool vv[4], gg[4]; const float* xq[4];
    #pragma unroll
    for (int j = 0; j < 4; ++j) {
        int e = u + j * 64;
        bool valid = (j < np) && (e < nelems);
        int ec = valid ? e : 0;
        int rl = ec / I_DIM, ii = ec - rl * I_DIM;
        int grow = row0 + 2 * pb + rl;
        vv[j] = valid;
        gg[j] = valid && (grow < B_DIM);
        xq[j] = x + (size_t)(gg[j] ? grow : 0) * TI + ii;
        sl[j] = ii * ST_F + 2 * pb + rl;
    }
    // prologue staging: x(0) -> buf0 (all groups); ORDER1 groups also x(1) -> buf1
    {
        float* x0 = (float*)sxT;
        float* x1 = (float*)(sxT + I_DIM * ST);
        #pragma unroll
        for (int j = 0; j < 4; ++j) {
            if (vv[j]) {
                x0[sl[j]] = gg[j] ? xq[j][0] : 0.0f;
                if (q >= 2) x1[sl[j]] = gg[j] ? xq[j][I_DIM] : 0.0f;
            }
        }
    }

    __syncthreads();   // weights + biases + h0 + staged x visible
    float4 bv = sb[u];
    u64 bi = pack2(bv.x, bv.x), bf = pack2(bv.y, bv.y);
    u64 bg = pack2(bv.z, bv.z), bo = pack2(bv.w, bv.w);

    if (q < 2) mainloop<4, 0>(sWih, sWhh, shT, sxT, u, pb, barid, bi, bf, bg, bo, xq, gg, vv, sl);
    else       mainloop<3, 1>(sWih, sWhh, shT, sxT, u, pb, barid, bi, bf, bg, bo, xq, gg, vv, sl);

    __syncthreads();   // all groups' h(T) visible

    // ---- output head: T=128 even -> final h in buffer 0; h[k][r] at float k*ST_F + r ----
    const float* hf = (const float*)shT;
    for (int e = tid; e < ROWS * OUT_DIM; e += THREADS) {
        int r = e / OUT_DIM, o = e - r * OUT_DIM;
        if (row0 + r < B_DIM) {
            float a = b_out[o];
            #pragma unroll
            for (int k = 0; k < H_DIM; ++k)
                a = fmaf(hf[k * ST_F + r], W_out[o * H_DIM + k], a);
            out[(size_t)(row0 + r) * OUT_DIM + o] = a;
        }
    }
}

extern "C" void kernel_launch(void* const* d_in, const int* in_sizes, int n_in,
                              void* d_out, int out_size) {
    const float* x     = (const float*)d_in[0];
    const float* W_ih  = (const float*)d_in[1];
    const float* W_hh  = (const float*)d_in[2];
    const float* b_ih  = (const float*)d_in[3];
    const float* b_hh  = (const float*)d_in[4];
    const float* W_out = (const float*)d_in[5];
    const float* b_out = (const float*)d_in[6];
    float* out = (float*)d_out;

    cudaFuncSetAttribute(lstm_kernel, cudaFuncAttributeMaxDynamicSharedMemorySize, SMEM_BYTES);
    lstm_kernel<<<NBLOCKS, THREADS, SMEM_BYTES>>>(x, W_ih, W_hh, b_ih, b_hh, W_out, b_out, out);
}

// round 16
// speedup vs baseline: 2.0586x; 1.6355x over previous
#include <cuda_runtime.h>
#include <cuda_fp16.h>
#include <cstdint>

#define I_DIM 28
#define H_DIM 64
#define T_DIM 128
#define B_DIM 4096
#define OUT_DIM 10
#define TI (T_DIM * I_DIM)          // 3584
#define TB 32                       // batch rows per CTA
#define THREADS 256
#define NBLOCKS 128                 // 128 * 32 = 4096 exactly
#define DS 36                       // dsm row stride (floats): float4-aligned, low-conflict
#define VST 104                     // v row stride (halves): bank-conflict-free B-frag loads

// ---- smem layout (bytes) ----
#define A_VER_BYTES (8*2*6*32*16)                 // 49152 per version (hi / lo)
#define OFF_A    0
#define OFF_V    (2 * A_VER_BYTES)                // 98304: [buf][ver][n=32][VST] halves
#define V_HALVES (2*2*32*VST)                     // 13312 halves = 26624 B
#define OFF_DSM  (OFF_V + V_HALVES*2)             // 124928: 256 x 36 f32
#define OFF_BIAS (OFF_DSM + 256*DS*4)             // 161792
#define SMEM_BYTES (OFF_BIAS + 1024)              // 162816

typedef unsigned long long u64;

// ---- PROVEN activations (end-to-end rel_err 2.9e-7; tanh.approx is NOT safe here) ----
__device__ __forceinline__ float rcpa(float x) { float r; asm("rcp.approx.f32 %0, %1;" : "=f"(r) : "f"(x)); return r; }
__device__ __forceinline__ float ex2a(float x) { float r; asm("ex2.approx.f32 %0, %1;" : "=f"(r) : "f"(x)); return r; }
__device__ __forceinline__ float sigm(float x)  { return rcpa(1.0f + ex2a(-1.4426950408889634f * x)); }
__device__ __forceinline__ float tanh_(float x) { return fmaf(2.0f, rcpa(1.0f + ex2a(-2.8853900817779268f * x)), -1.0f); }

// m16n8k16 f16 MMA, f32 accumulate (baseline PTX, sm_80+; runs on HMMA pipe)
#define MMA(d, a, b) \
    asm volatile("mma.sync.aligned.m16n8k16.row.col.f32.f16.f16.f32 " \
        "{%0,%1,%2,%3}, {%4,%5,%6,%7}, {%8,%9}, {%0,%1,%2,%3};" \
        : "+f"((d)[0]), "+f"((d)[1]), "+f"((d)[2]), "+f"((d)[3]) \
        : "r"((a).x), "r"((a).y), "r"((a).z), "r"((a).w), "r"((b)[0]), "r"((b)[1]))

__device__ __forceinline__ void h2split(float v, __half& hi, __half& lo) {
    hi = __float2half_rn(v);
    lo = __float2half_rn(v - __half2float(hi));
}

__global__ void __launch_bounds__(THREADS, 1)
lstm_kernel(const float* __restrict__ x,
            const float* __restrict__ W_ih,
            const float* __restrict__ W_hh,
            const float* __restrict__ b_ih,
            const float* __restrict__ b_hh,
            const float* __restrict__ W_out,
            const float* __restrict__ b_out,
            float* __restrict__ out)
{
    extern __shared__ char smc[];
    __half* vh   = (__half*)(smc + OFF_V);
    float*  dsm  = (float*)(smc + OFF_DSM);
    float*  sbias= (float*)(smc + OFF_BIAS);
    const uint4* smA = (const uint4*)(smc + OFF_A);

    const int tid  = threadIdx.x;
    const int wid  = tid >> 5;
    const int lane = tid & 31;
    const int g    = lane >> 2;       // fragment group row
    const int tq   = lane & 3;        // thread-in-group
    const int u    = tid & 63;        // hidden unit (epilogue)
    const int rg   = tid >> 6;        // row group of 8 (epilogue)
    const int rbase = rg << 3;
    const int r0 = blockIdx.x * TB;

    // ---- stage A fragments (weights, hi+lo fp16) in exact m16n8k16 layout ----
    // linear idx = (((w*2+mt)*6+kt)*32 + lane)*4 + reg  (12288 half2 slots per version)
    for (int idx = tid; idx < 12288; idx += THREADS) {
        int reg = idx & 3;
        int ln  = (idx >> 2) & 31;
        int kt  = (idx >> 7) % 6;
        int mtw = (idx >> 7) / 6;
        int mt = mtw & 1, w = mtw >> 1;
        int gg = ln >> 2, tt = ln & 3;
        int row = w * 32 + mt * 16 + gg + (reg & 1) * 8;          // gate index 0..255
        int c0  = kt * 16 + 2 * tt + (reg >> 1) * 8;              // k index 0..95
        int c1  = c0 + 1;
        float f0 = (c0 < 64) ? W_hh[row * H_DIM + c0] : (c0 < 92 ? W_ih[row * I_DIM + c0 - 64] : 0.0f);
        float f1 = (c1 < 64) ? W_hh[row * H_DIM + c1] : (c1 < 92 ? W_ih[row * I_DIM + c1 - 64] : 0.0f);
        __half h0, l0, h1, l1;
        h2split(f0, h0, l0); h2split(f1, h1, l1);
        __half2 hp; hp.x = h0; hp.y = h1;
        __half2 lp; lp.x = l0; lp.y = l1;
        ((__half2*)(smc + OFF_A))[idx] = hp;
        ((__half2*)(smc + OFF_A + A_VER_BYTES))[idx] = lp;
    }
    if (tid < 256) sbias[tid] = b_ih[tid] + b_hh[tid];
    // zero v (both buffers, both versions) -> h(0)=0 and K-pad stays 0 forever
    for (int i2 = tid; i2 < (int)(V_HALVES * 2 / 8); i2 += THREADS)
        ((u64*)vh)[i2] = 0ull;

    // ---- per-thread x staging slots (896 = 32 rows x 28) ----
    const float* xptr[4]; int xrow[4], xcol[4]; bool xv[4];
    #pragma unroll
    for (int j = 0; j < 4; ++j) {
        int e = tid + j * THREADS;
        xv[j] = (e < TB * I_DIM);
        int ec = xv[j] ? e : 0;
        xrow[j] = ec / I_DIM;
        xcol[j] = ec - xrow[j] * I_DIM;
        xptr[j] = x + (size_t)(r0 + xrow[j]) * TI + xcol[j];
    }
    __syncthreads();   // v zeroed before x(0) staging (avoid store-order race with zeroers)
    // stage x(0) into buf 0
    #pragma unroll
    for (int j = 0; j < 4; ++j) if (xv[j]) {
        __half hi, lo; h2split(xptr[j][0], hi, lo);
        vh[(0 * 32 + xrow[j]) * VST + 64 + xcol[j]] = hi;     // buf0 ver0
        vh[(1 * 32 + xrow[j]) * VST + 64 + xcol[j]] = lo;     // buf0 ver1
    }

    float cst[8], hT[8];
    #pragma unroll
    for (int j = 0; j < 8; ++j) { cst[j] = 0.0f; hT[j] = 0.0f; }

    __syncthreads();   // A frags + bias + v ready
    const float bI = sbias[u], bF = sbias[64 + u], bG = sbias[128 + u], bO = sbias[192 + u];

    for (int t = 0; t < T_DIM; ++t) {
        const int cur = t & 1, nxt = cur ^ 1;
        // gmem prefetch of x(t+1), hidden under the MMA block
        float xpre[4];
        if (t + 1 < T_DIM) {
            #pragma unroll
            for (int j = 0; j < 4; ++j)
                xpre[j] = xv[j] ? xptr[j][(t + 1) * I_DIM] : 0.0f;
        }

        // ---- MMA block: D[32 gates][32 rows] per warp, 3-term fp16 split ----
        float d[2][4][4];
        #pragma unroll
        for (int mt = 0; mt < 2; ++mt)
            #pragma unroll
            for (int nt = 0; nt < 4; ++nt)
                #pragma unroll
                for (int e2 = 0; e2 < 4; ++e2) d[mt][nt][e2] = 0.0f;

        const __half* vbh = vh + (cur * 2 + 0) * 32 * VST;
        const __half* vbl = vh + (cur * 2 + 1) * 32 * VST;
        #pragma unroll
        for (int kt = 0; kt < 6; ++kt) {
            uint4 Ah[2], Al[2];
            #pragma unroll
            for (int mt = 0; mt < 2; ++mt) {
                int fo = ((wid * 2 + mt) * 6 + kt) * 32 + lane;
                Ah[mt] = smA[fo];
                Al[mt] = smA[(A_VER_BYTES / 16) + fo];
            }
            uint32_t bh[4][2], bl[4][2];
            #pragma unroll
            for (int nt = 0; nt < 4; ++nt) {
                int n = nt * 8 + g;
                const __half* ph = vbh + n * VST + kt * 16 + 2 * tq;
                const __half* pl = vbl + n * VST + kt * 16 + 2 * tq;
                bh[nt][0] = *(const uint32_t*)ph;
                bh[nt][1] = *(const uint32_t*)(ph + 8);
                bl[nt][0] = *(const uint32_t*)pl;
                bl[nt][1] = *(const uint32_t*)(pl + 8);
            }
            #pragma unroll
            for (int mt = 0; mt < 2; ++mt)
                #pragma unroll
                for (int nt = 0; nt < 4; ++nt) {
                    MMA(d[mt][nt], Ah[mt], bh[nt]);   // hi*hi
                    MMA(d[mt][nt], Ah[mt], bl[nt]);   // hi*lo
                    MMA(d[mt][nt], Al[mt], bh[nt]);   // lo*hi
                }
        }

        // ---- D -> dsm exchange ----
        #pragma unroll
        for (int mt = 0; mt < 2; ++mt)
            #pragma unroll
            for (int nt = 0; nt < 4; ++nt) {
                int gr = wid * 32 + mt * 16 + g;
                int cb = nt * 8 + 2 * tq;
                *(float2*)&dsm[gr * DS + cb]       = make_float2(d[mt][nt][0], d[mt][nt][1]);
                *(float2*)&dsm[(gr + 8) * DS + cb] = make_float2(d[mt][nt][2], d[mt][nt][3]);
            }
        __syncthreads();   // dsm complete

        // ---- epilogue: thread = (unit u, rows rbase..rbase+7) ----
        float4 Gi0 = *(const float4*)&dsm[u * DS + rbase];
        float4 Gi1 = *(const float4*)&dsm[u * DS + rbase + 4];
        float4 Gf0 = *(const float4*)&dsm[(64 + u) * DS + rbase];
        float4 Gf1 = *(const float4*)&dsm[(64 + u) * DS + rbase + 4];
        float4 Gg0 = *(const float4*)&dsm[(128 + u) * DS + rbase];
        float4 Gg1 = *(const float4*)&dsm[(128 + u) * DS + rbase + 4];
        float4 Go0 = *(const float4*)&dsm[(192 + u) * DS + rbase];
        float4 Go1 = *(const float4*)&dsm[(192 + u) * DS + rbase + 4];
        float gi[8] = {Gi0.x,Gi0.y,Gi0.z,Gi0.w,Gi1.x,Gi1.y,Gi1.z,Gi1.w};
        float gf[8] = {Gf0.x,Gf0.y,Gf0.z,Gf0.w,Gf1.x,Gf1.y,Gf1.z,Gf1.w};
        float gG[8] = {Gg0.x,Gg0.y,Gg0.z,Gg0.w,Gg1.x,Gg1.y,Gg1.z,Gg1.w};
        float go[8] = {Go0.x,Go0.y,Go0.z,Go0.w,Go1.x,Go1.y,Go1.z,Go1.w};

        if (t + 1 < T_DIM) {
            __half* nh = vh + (nxt * 2 + 0) * 32 * VST;
            __half* nl = vh + (nxt * 2 + 1) * 32 * VST;
            #pragma unroll
            for (int j = 0; j < 8; ++j) {
                float iv = sigm(gi[j] + bI);
                float fv = sigm(gf[j] + bF);
                float gv = tanh_(gG[j] + bG);
                float ov = sigm(go[j] + bO);
                cst[j] = fmaf(fv, cst[j], iv * gv);
                float hv = ov * tanh_(cst[j]);
                __half hi, lo; h2split(hv, hi, lo);
                nh[(rbase + j) * VST + u] = hi;
                nl[(rbase + j) * VST + u] = lo;
            }
            // stage x(t+1)
            #pragma unroll
            for (int j = 0; j < 4; ++j) if (xv[j]) {
                __half hi, lo; h2split(xpre[j], hi, lo);
                nh[xrow[j] * VST + 64 + xcol[j]] = hi;
                nl[xrow[j] * VST + 64 + xcol[j]] = lo;
            }
        } else {
            #pragma unroll
            for (int j = 0; j < 8; ++j) {
                float iv = sigm(gi[j] + bI);
                float fv = sigm(gf[j] + bF);
                float gv = tanh_(gG[j] + bG);
                float ov = sigm(go[j] + bO);
                cst[j] = fmaf(fv, cst[j], iv * gv);
                hT[j] = ov * tanh_(cst[j]);
            }
        }
        __syncthreads();   // v[nxt] ready; dsm consumed
    }

    // ---- output head: h_T (fp32) via dsm ----
    {
        float* dst = dsm + u * DS + rbase;
        #pragma unroll
        for (int j = 0; j < 8; ++j) dst[j] = hT[j];   // dsm[u][row] = h_T[row][u]
    }
    __syncthreads();
    for (int e = tid; e < TB * OUT_DIM; e += THREADS) {
        int r = e / OUT_DIM, o = e - r * OUT_DIM;
        float a = b_out[o];
        #pragma unroll
        for (int k = 0; k < H_DIM; ++k)
            a = fmaf(dsm[k * DS + r], W_out[o * H_DIM + k], a);
        out[(size_t)(r0 + r) * OUT_DIM + o] = a;
    }
}

extern "C" void kernel_launch(void* const* d_in, const int* in_sizes, int n_in,
                              void* d_out, int out_size) {
    const float* x     = (const float*)d_in[0];
    const float* W_ih  = (const float*)d_in[1];
    const float* W_hh  = (const float*)d_in[2];
    const float* b_ih  = (const float*)d_in[3];
    const float* b_hh  = (const float*)d_in[4];
    const float* W_out = (const float*)d_in[5];
    const float* b_out = (const float*)d_in[6];
    float* out = (float*)d_out;

    cudaFuncSetAttribute(lstm_kernel, cudaFuncAttributeMaxDynamicSharedMemorySize, SMEM_BYTES);
    lstm_kernel<<<NBLOCKS, THREADS, SMEM_BYTES>>>(x, W_ih, W_hh, b_ih, b_hh, W_out, b_out, out);
}

// round 17
// speedup vs baseline: 2.2203x; 1.0785x over previous
#include <cuda_runtime.h>
#include <cuda_fp16.h>
#include <cstdint>

#define I_DIM 28
#define H_DIM 64
#define T_DIM 128
#define B_DIM 4096
#define OUT_DIM 10
#define TI (T_DIM * I_DIM)          // 3584
#define TB 32                       // batch rows per CTA
#define THREADS 256
#define NBLOCKS 128                 // 128 * 32 = 4096
#define VST 104                     // v row stride (halves)

// ---- smem layout (bytes) ----
#define A_VER_BYTES (8*2*6*32*16)                 // 49152 per version (hi / lo)
#define OFF_A    0
#define OFF_V    (2 * A_VER_BYTES)                // 98304: [buf][ver][n=32][VST] halves
#define V_BYTES  (2*2*32*VST*2)                   // 26624
#define OFF_BIAS (OFF_V + V_BYTES)                // 124928
#define SMEM_BYTES (OFF_BIAS + 1024)              // 125952

typedef unsigned long long u64;

// ---- PROVEN activations (end-to-end rel_err ~3e-7; tanh.approx is NOT safe here) ----
__device__ __forceinline__ float rcpa(float x) { float r; asm("rcp.approx.f32 %0, %1;" : "=f"(r) : "f"(x)); return r; }
__device__ __forceinline__ float ex2a(float x) { float r; asm("ex2.approx.f32 %0, %1;" : "=f"(r) : "f"(x)); return r; }
__device__ __forceinline__ float sigm(float x)  { return rcpa(1.0f + ex2a(-1.4426950408889634f * x)); }
__device__ __forceinline__ float tanh_(float x) { return fmaf(2.0f, rcpa(1.0f + ex2a(-2.8853900817779268f * x)), -1.0f); }

#define MMA(d, a, b) \
    asm volatile("mma.sync.aligned.m16n8k16.row.col.f32.f16.f16.f32 " \
        "{%0,%1,%2,%3}, {%4,%5,%6,%7}, {%8,%9}, {%0,%1,%2,%3};" \
        : "+f"((d)[0]), "+f"((d)[1]), "+f"((d)[2]), "+f"((d)[3]) \
        : "r"((a).x), "r"((a).y), "r"((a).z), "r"((a).w), "r"((b)[0]), "r"((b)[1]))

__device__ __forceinline__ void h2split(float v, __half& hi, __half& lo) {
    hi = __float2half_rn(v);
    lo = __float2half_rn(v - __half2float(hi));
}

// MMA span over k-tiles [KB,KE): 3-term fp16 split, accumulate into d.
template<int KB, int KE>
__device__ __forceinline__ void mma_span(float (&d)[2][4][4], const uint4* __restrict__ smA,
                                         const __half* __restrict__ vbh,
                                         const __half* __restrict__ vbl,
                                         int wid, int lane)
{
    const int g = lane >> 2, tq = lane & 3;
    #pragma unroll
    for (int kt = KB; kt < KE; ++kt) {
        uint4 Ah[2], Al[2];
        #pragma unroll
        for (int mt = 0; mt < 2; ++mt) {
            int fo = ((wid * 2 + mt) * 6 + kt) * 32 + lane;
            Ah[mt] = smA[fo];
            Al[mt] = smA[(A_VER_BYTES / 16) + fo];
        }
        uint32_t bh[4][2], bl[4][2];
        #pragma unroll
        for (int nt = 0; nt < 4; ++nt) {
            int n = nt * 8 + g;
            const __half* ph = vbh + n * VST + kt * 16 + 2 * tq;
            const __half* pl = vbl + n * VST + kt * 16 + 2 * tq;
            bh[nt][0] = *(const uint32_t*)ph; bh[nt][1] = *(const uint32_t*)(ph + 8);
            bl[nt][0] = *(const uint32_t*)pl; bl[nt][1] = *(const uint32_t*)(pl + 8);
        }
        #pragma unroll
        for (int mt = 0; mt < 2; ++mt)
            #pragma unroll
            for (int nt = 0; nt < 4; ++nt) {
                MMA(d[mt][nt], Ah[mt], bh[nt]);   // hi*hi
                MMA(d[mt][nt], Ah[mt], bl[nt]);   // hi*lo
                MMA(d[mt][nt], Al[mt], bh[nt]);   // lo*hi
            }
    }
}

__global__ void __launch_bounds__(THREADS, 1)
lstm_kernel(const float* __restrict__ x,
            const float* __restrict__ W_ih,
            const float* __restrict__ W_hh,
            const float* __restrict__ b_ih,
            const float* __restrict__ b_hh,
            const float* __restrict__ W_out,
            const float* __restrict__ b_out,
            float* __restrict__ out)
{
    extern __shared__ char smc[];
    __half* vh    = (__half*)(smc + OFF_V);
    float*  sbias = (float*)(smc + OFF_BIAS);
    const uint4* smA = (const uint4*)(smc + OFF_A);

    const int tid  = threadIdx.x;
    const int wid  = tid >> 5;
    const int lane = tid & 31;
    const int g    = lane >> 2;
    const int tq   = lane & 3;
    const int u    = wid * 8 + g;     // this thread's hidden unit (all 4 gates in-register)
    const int r0 = blockIdx.x * TB;

    // ---- stage A fragments: M-permuted so gate b of unit u = warp-row b*8+... ----
    // m_warp = mt*16 + gg + 8*(reg&1):  gate = mt*2 + (reg&1), unit = wid*8 + gg
    for (int idx = tid; idx < 12288; idx += THREADS) {
        int reg = idx & 3;
        int ln  = (idx >> 2) & 31;
        int kt  = (idx >> 7) % 6;
        int mtw = (idx >> 7) / 6;
        int mt = mtw & 1, w = mtw >> 1;
        int gg = ln >> 2, tt = ln & 3;
        int gate = mt * 2 + (reg & 1);
        int row  = gate * 64 + w * 8 + gg;                 // W row (PyTorch i,f,g,o)
        int c0   = kt * 16 + 2 * tt + (reg >> 1) * 8;      // k 0..95
        int c1   = c0 + 1;
        float f0 = (c0 < 64) ? W_hh[row * H_DIM + c0] : (c0 < 92 ? W_ih[row * I_DIM + c0 - 64] : 0.0f);
        float f1 = (c1 < 64) ? W_hh[row * H_DIM + c1] : (c1 < 92 ? W_ih[row * I_DIM + c1 - 64] : 0.0f);
        __half h0, l0, h1, l1;
        h2split(f0, h0, l0); h2split(f1, h1, l1);
        __half2 hp; hp.x = h0; hp.y = h1;
        __half2 lp; lp.x = l0; lp.y = l1;
        ((__half2*)(smc + OFF_A))[idx] = hp;
        ((__half2*)(smc + OFF_A + A_VER_BYTES))[idx] = lp;
    }
    if (tid < 256) sbias[tid] = b_ih[tid] + b_hh[tid];
    // zero v (both buffers/versions): h(0)=0, x K-pad stays 0
    for (int i2 = tid; i2 < (int)(V_BYTES / 8); i2 += THREADS)
        ((u64*)vh)[i2] = 0ull;

    // ---- per-thread x staging slots (896 = 32 rows x 28) ----
    const float* xptr[4]; int xrow[4], xcol[4]; bool xv[4];
    #pragma unroll
    for (int j = 0; j < 4; ++j) {
        int e = tid + j * THREADS;
        xv[j] = (e < TB * I_DIM);
        int ec = xv[j] ? e : 0;
        xrow[j] = ec / I_DIM;
        xcol[j] = ec - xrow[j] * I_DIM;
        xptr[j] = x + (size_t)(r0 + xrow[j]) * TI + xcol[j];
    }
    __syncthreads();   // v zeroed before x staging
    // stage x(0) -> buf0, x(1) -> buf1
    #pragma unroll
    for (int j = 0; j < 4; ++j) if (xv[j]) {
        __half hi, lo;
        h2split(xptr[j][0], hi, lo);
        vh[(0 * 32 + xrow[j]) * VST + 64 + xcol[j]] = hi;
        vh[(1 * 32 + xrow[j]) * VST + 64 + xcol[j]] = lo;
        h2split(xptr[j][I_DIM], hi, lo);
        vh[(2 * 32 + xrow[j]) * VST + 64 + xcol[j]] = hi;
        vh[(3 * 32 + xrow[j]) * VST + 64 + xcol[j]] = lo;
    }

    float cst[8];
    #pragma unroll
    for (int j = 0; j < 8; ++j) cst[j] = 0.0f;

    __syncthreads();   // A frags + bias + v ready
    const float bI = sbias[u], bF = sbias[64 + u], bG = sbias[128 + u], bO = sbias[192 + u];

    float d[2][4][4];
    #pragma unroll
    for (int mt = 0; mt < 2; ++mt)
        #pragma unroll
        for (int nt = 0; nt < 4; ++nt)
            #pragma unroll
            for (int e2 = 0; e2 < 4; ++e2) d[mt][nt][e2] = 0.0f;

    // pre-loop: x-projection for t=0 (reads v[0].x)
    mma_span<4, 6>(d, smA, vh + 0 * 32 * VST, vh + 1 * 32 * VST, wid, lane);

    for (int t = 0; t < T_DIM; ++t) {
        const int p = t & 1, pn = p ^ 1;
        // gmem prefetch of x(t+2) (hidden under h-MMAs)
        float xpre[4];
        if (t + 2 < T_DIM) {
            #pragma unroll
            for (int j = 0; j < 4; ++j)
                xpre[j] = xv[j] ? xptr[j][(t + 2) * I_DIM] : 0.0f;
        }

        // h-projection MMAs (k-tiles 0..3) accumulate onto carried x-projection
        mma_span<0, 4>(d, smA, vh + (p * 2 + 0) * 32 * VST, vh + (p * 2 + 1) * 32 * VST, wid, lane);

        // ---- in-register epilogue: this thread owns all 4 gates of unit u, 8 cols ----
        if (t + 1 < T_DIM) {
            __half* nh = vh + (pn * 2 + 0) * 32 * VST;
            __half* nl = vh + (pn * 2 + 1) * 32 * VST;
            #pragma unroll
            for (int nt = 0; nt < 4; ++nt)
                #pragma unroll
                for (int e2 = 0; e2 < 2; ++e2) {
                    int s = nt * 2 + e2;
                    int col = nt * 8 + 2 * tq + e2;
                    float iv = sigm(d[0][nt][e2]     + bI);
                    float fv = sigm(d[0][nt][2 + e2] + bF);
                    float gv = tanh_(d[1][nt][e2]     + bG);
                    float ov = sigm(d[1][nt][2 + e2] + bO);
                    cst[s] = fmaf(fv, cst[s], iv * gv);
                    float hv = ov * tanh_(cst[s]);
                    __half hi, lo; h2split(hv, hi, lo);
                    nh[col * VST + u] = hi;
                    nl[col * VST + u] = lo;
                }
            // protect x(2) staging against other warps' pre-loop x-MMA(0)
            if (t == 0) __syncthreads();
            // stage x(t+2) into buffer p (its x was consumed by x-MMA(t), done pre-barrier(t-1))
            if (t + 2 < T_DIM) {
                __half* sh = vh + (p * 2 + 0) * 32 * VST;
                __half* sl = vh + (p * 2 + 1) * 32 * VST;
                #pragma unroll
                for (int j = 0; j < 4; ++j) if (xv[j]) {
                    __half hi, lo; h2split(xpre[j], hi, lo);
                    sh[xrow[j] * VST + 64 + xcol[j]] = hi;
                    sl[xrow[j] * VST + 64 + xcol[j]] = lo;
                }
            }
            // reset accumulators and issue x-projection for t+1 (reads v[pn].x, staged at t-1).
            // Independent of the MUFU epilogue chain -> scheduler overlaps them.
            #pragma unroll
            for (int mt = 0; mt < 2; ++mt)
                #pragma unroll
                for (int nt = 0; nt < 4; ++nt)
                    #pragma unroll
                    for (int e2 = 0; e2 < 4; ++e2) d[mt][nt][e2] = 0.0f;
            mma_span<4, 6>(d, smA, vh + (pn * 2 + 0) * 32 * VST, vh + (pn * 2 + 1) * 32 * VST, wid, lane);
            __syncthreads();   // h(t+1) + staged x visible; single barrier per step
        } else {
            // final step: keep h in cst
            #pragma unroll
            for (int nt = 0; nt < 4; ++nt)
                #pragma unroll
                for (int e2 = 0; e2 < 2; ++e2) {
                    int s = nt * 2 + e2;
                    float iv = sigm(d[0][nt][e2]     + bI);
                    float fv = sigm(d[0][nt][2 + e2] + bF);
                    float gv = tanh_(d[1][nt][e2]     + bG);
                    float ov = sigm(d[1][nt][2 + e2] + bO);
                    cst[s] = fmaf(fv, cst[s], iv * gv);
                    cst[s] = ov * tanh_(cst[s]);   // overwrite with h_T
                }
        }
    }

    // ---- output head: reuse A region as fp32 scratch h[u][col] (stride 33) ----
    __syncthreads();   // all warps done reading A frags
    float* hsc = (float*)smc;
    #pragma unroll
    for (int nt = 0; nt < 4; ++nt)
        #pragma unroll
        for (int e2 = 0; e2 < 2; ++e2)
            hsc[u * 33 + nt * 8 + 2 * tq + e2] = cst[nt * 2 + e2];
    __syncthreads();
    for (int e = tid; e < TB * OUT_DIM; e += THREADS) {
        int r = e / OUT_DIM, o = e - r * OUT_DIM;
        float a = b_out[o];
        #pragma unroll
        for (int k = 0; k < H_DIM; ++k)
            a = fmaf(hsc[k * 33 + r], W_out[o * H_DIM + k], a);
        out[(size_t)(r0 + r) * OUT_DIM + o] = a;
    }
}

extern "C" void kernel_launch(void* const* d_in, const int* in_sizes, int n_in,
                              void* d_out, int out_size) {
    const float* x     = (const float*)d_in[0];
    const float* W_ih  = (const float*)d_in[1];
    const float* W_hh  = (const float*)d_in[2];
    const float* b_ih  = (const float*)d_in[3];
    const float* b_hh  = (const float*)d_in[4];
    const float* W_out = (const float*)d_in[5];
    const float* b_out = (const float*)d_in[6];
    float* out = (float*)d_out;

    cudaFuncSetAttribute(lstm_kernel, cudaFuncAttributeMaxDynamicSharedMemorySize, SMEM_BYTES);
    lstm_kernel<<<NBLOCKS, THREADS, SMEM_BYTES>>>(x, W_ih, W_hh, b_ih, b_hh, W_out, b_out, out);
}